// round 16
// baseline (speedup 1.0000x reference)
#include <cuda_runtime.h>
#include <cuda_fp16.h>
#include <math.h>
#include <stdint.h>

// ---------------- problem constants ----------------
namespace {
constexpr int Bn    = 16;
constexpr int E     = 768;
constexpr int HEADS = 12;
constexpr int Ll    = 12;
constexpr int MLPD  = 3072;
constexpr int OUTD  = 2048;
constexpr int PW    = 42;
constexpr int NPAT  = 168;
constexpr int SEQ   = 169;
constexpr int Nrow  = 2704;
constexpr int DH    = 64;
constexpr int E3    = 2304;
constexpr int E2    = 1536;
}

// ---------------- scratch (static device globals) ----------------
__device__ __align__(16) float  g_X   [Nrow * E];
__device__ __align__(16) __half g_XN  [Nrow * E];
__device__ __align__(16) float  g_QKV [Nrow * E3];
__device__ __align__(16) __half g_O   [Nrow * E];
__device__ __align__(16) __half g_H1  [Nrow * MLPD];
__device__ __align__(16) __half g_PT  [Bn * NPAT * E];
__device__ __align__(16) float  g_PE  [Bn * NPAT * E];
__device__ __align__(16) float  g_OUTP[Nrow * OUTD];

// pre-converted fp16 weights
__device__ __align__(16) __half g_Wpatch[768 * 768];
__device__ __align__(16) __half g_Win   [12 * 2304 * 768];
__device__ __align__(16) __half g_Wout  [12 * 768 * 768];
__device__ __align__(16) __half g_Wm1   [12 * 3072 * 768];
__device__ __align__(16) __half g_Wm2   [12 * 768 * 3072];
__device__ __align__(16) __half g_Wb1   [1536 * 768];
__device__ __align__(16) __half g_Wb2   [2048 * 1536];

// ---------------- fp16 helpers ----------------
__device__ __forceinline__ uint32_t f2h2(float a, float b)
{
    __half2 h = __halves2half2(__float2half_rn(a), __float2half_rn(b));
    return *(uint32_t*)&h;
}

__device__ __forceinline__ void mma_f16(float* c, const uint32_t* a, const uint32_t* b)
{
    asm volatile(
        "mma.sync.aligned.m16n8k16.row.col.f32.f16.f16.f32 "
        "{%0,%1,%2,%3}, {%4,%5,%6,%7}, {%8,%9}, {%0,%1,%2,%3};\n"
        : "+f"(c[0]), "+f"(c[1]), "+f"(c[2]), "+f"(c[3])
        : "r"(a[0]), "r"(a[1]), "r"(a[2]), "r"(a[3]), "r"(b[0]), "r"(b[1]));
}

__device__ __forceinline__ void ldm_x4(uint32_t* r, uint32_t saddr)
{
    asm volatile("ldmatrix.sync.aligned.m8n8.x4.shared.b16 {%0,%1,%2,%3}, [%4];"
                 : "=r"(r[0]), "=r"(r[1]), "=r"(r[2]), "=r"(r[3]) : "r"(saddr));
}

// ---------------- weight conversion (8 floats -> 8 halves per thread) -------
__global__ void cvt_kernel(const float* __restrict__ src, __half* __restrict__ dst, int n8)
{
    int i = blockIdx.x * blockDim.x + threadIdx.x;
    if (i >= n8) return;
    float4 v0 = ((const float4*)src)[2 * i];
    float4 v1 = ((const float4*)src)[2 * i + 1];
    uint4 o;
    o.x = f2h2(v0.x, v0.y);
    o.y = f2h2(v0.z, v0.w);
    o.z = f2h2(v1.x, v1.y);
    o.w = f2h2(v1.z, v1.w);
    ((uint4*)dst)[i] = o;
}

// ---------------- patchify (writes fp16) ----------------
__global__ void patchify_kernel(const float* __restrict__ px, __half* __restrict__ PT)
{
    int idx = blockIdx.x * blockDim.x + threadIdx.x;
    if (idx >= Bn * NPAT * E) return;
    int k = idx % E;
    int m = idx / E;
    int b = m / NPAT, p = m % NPAT;
    int ph = p / PW, pw = p % PW;
    int c  = k >> 8;
    int r  = k & 255;
    int ii = r >> 4, jj = r & 15;
    PT[idx] = __float2half_rn(px[(((size_t)(b * 3 + c) * 64 + ph * 16 + ii) * 672) + pw * 16 + jj]);
}

// ---------------- assemble ----------------
__global__ void assemble_kernel(const float* __restrict__ PE_, const float* __restrict__ cls,
                                const float* __restrict__ row_emb, const float* __restrict__ col_emb,
                                float* __restrict__ X)
{
    int idx = blockIdx.x * blockDim.x + threadIdx.x;
    if (idx >= Nrow * E) return;
    int e = idx % E;
    int n = idx / E;
    int b = n / SEQ, s = n % SEQ;
    float v;
    if (s == 0) {
        v = cls[e];
    } else {
        int p = s - 1, ph = p / PW, pw = p % PW;
        float pos = (e < 384) ? row_emb[ph * 384 + e] : col_emb[pw * 384 + (e - 384)];
        v = PE_[((size_t)(b * NPAT) + p) * E + e] + pos;
    }
    X[idx] = v;
}

// ---------------- LayerNorm (float4-vectorized; optional fp16 output) -------
__global__ void ln_kernel(const float* __restrict__ x, const float* __restrict__ g,
                          const float* __restrict__ b, void* __restrict__ y, int D, int cvtout)
{
    int row = blockIdx.x;
    const float4* xr = (const float4*)(x + (size_t)row * D);
    const int D4 = D >> 2;
    float s = 0.f, s2 = 0.f;
    for (int i = threadIdx.x; i < D4; i += blockDim.x) {
        float4 v = xr[i];
        s  += v.x + v.y + v.z + v.w;
        s2 += v.x * v.x + v.y * v.y + v.z * v.z + v.w * v.w;
    }
    __shared__ float shs[8], shs2[8];
    #pragma unroll
    for (int o = 16; o; o >>= 1) {
        s  += __shfl_xor_sync(~0u, s,  o);
        s2 += __shfl_xor_sync(~0u, s2, o);
    }
    int w = threadIdx.x >> 5, lane = threadIdx.x & 31;
    if (lane == 0) { shs[w] = s; shs2[w] = s2; }
    __syncthreads();
    if (w == 0) {
        s  = lane < 8 ? shs[lane]  : 0.f;
        s2 = lane < 8 ? shs2[lane] : 0.f;
        #pragma unroll
        for (int o = 4; o; o >>= 1) {
            s  += __shfl_xor_sync(~0u, s,  o);
            s2 += __shfl_xor_sync(~0u, s2, o);
        }
        if (lane == 0) { shs[0] = s; shs2[0] = s2; }
    }
    __syncthreads();
    float m   = shs[0] / (float)D;
    float var = shs2[0] / (float)D - m * m;
    float inv = rsqrtf(var + 1e-5f);
    const float4* gp = (const float4*)g;
    const float4* bp = (const float4*)b;
    if (cvtout) {
        uint2* yr = (uint2*)((__half*)y + (size_t)row * D);
        for (int i = threadIdx.x; i < D4; i += blockDim.x) {
            float4 v = xr[i], gg = gp[i], bb = bp[i];
            uint2 o;
            o.x = f2h2((v.x - m) * inv * gg.x + bb.x, (v.y - m) * inv * gg.y + bb.y);
            o.y = f2h2((v.z - m) * inv * gg.z + bb.z, (v.w - m) * inv * gg.w + bb.w);
            yr[i] = o;
        }
    } else {
        float4* yr = (float4*)((float*)y + (size_t)row * D);
        for (int i = threadIdx.x; i < D4; i += blockDim.x) {
            float4 v = xr[i], gg = gp[i], bb = bp[i];
            float4 o;
            o.x = (v.x - m) * inv * gg.x + bb.x;
            o.y = (v.y - m) * inv * gg.y + bb.y;
            o.z = (v.z - m) * inv * gg.z + bb.z;
            o.w = (v.w - m) * inv * gg.w + bb.w;
            yr[i] = o;
        }
    }
}

// ---------------- GEMM epilogue helper ----------------
__device__ __forceinline__ void epi_store(void* Cout, size_t off, int c,
                                          float v0, float v1,
                                          const float* bias, const float* Res,
                                          int epi, int cvtout)
{
    v0 += bias[c];
    v1 += bias[c + 1];
    if (epi == 1) {
        v0 = 0.5f * v0 * (1.0f + erff(v0 * 0.70710678118654752f));
        v1 = 0.5f * v1 * (1.0f + erff(v1 * 0.70710678118654752f));
    } else if (epi == 2) {
        v0 += Res[off + c];
        v1 += Res[off + c + 1];
    }
    if (cvtout) {
        *(uint32_t*)((__half*)Cout + off + c) = f2h2(v0, v1);
    } else {
        *(float2*)((float*)Cout + off + c) = make_float2(v0, v1);
    }
}

// ---------------- FP16 GEMM, 128x128 tile, BK=32, ldmatrix (round-14) -------
constexpr int ROWB   = 80;               // bytes per smem row (64 data + 16 pad)
constexpr int STAGEB = 128 * ROWB;       // 10240 B per stage

__global__ __launch_bounds__(256) void gemm_tc(const __half* __restrict__ A,
                                               const __half* __restrict__ W,
                                               const float* __restrict__ bias,
                                               const float* __restrict__ Res,
                                               void* __restrict__ Cout,
                                               int M, int K, int Nout, int epi, int cvtout)
{
    __shared__ __align__(16) char sm[4 * STAGEB];
    const uint32_t smb = (uint32_t)__cvta_generic_to_shared(sm);

    const int t = threadIdx.x;
    const int warp = t >> 5, lane = t & 31;
    const int g = lane >> 2, q = lane & 3;
    const int warpM = (warp >> 1) * 32;
    const int warpN = (warp & 1) * 64;

    const int lrow = t >> 1;
    const int lks  = t & 1;
    int rowA = blockIdx.y * 128 + lrow;
    int rowW = blockIdx.x * 128 + lrow;
    if (rowA >= M) rowA = M - 1;
    const __half* Ap = A + (size_t)rowA * K + lks * 16;
    const __half* Wp = W + (size_t)rowW * K + lks * 16;
    char* const psA = sm + lrow * ROWB + lks * 32;
    char* const psB = psA + 2 * STAGEB;

    const uint32_t offA0 = (uint32_t)((warpM + (lane & 15)) * ROWB + (lane >> 4) * 16);
    const uint32_t offB0 = (uint32_t)((warpN + (lane & 7) + ((lane >> 4) << 3)) * ROWB
                                      + ((lane >> 3) & 1) * 16);

    float acc[2][8][4];
    #pragma unroll
    for (int mt = 0; mt < 2; mt++)
        #pragma unroll
        for (int nt = 0; nt < 8; nt++)
            #pragma unroll
            for (int i = 0; i < 4; i++) acc[mt][nt][i] = 0.f;

    const int nk = K >> 5;

    {
        uint4 a0 = *(const uint4*)(Ap);
        uint4 a1 = *(const uint4*)(Ap + 8);
        uint4 w0 = *(const uint4*)(Wp);
        uint4 w1 = *(const uint4*)(Wp + 8);
        *(uint4*)(psA)      = a0;
        *(uint4*)(psA + 16) = a1;
        *(uint4*)(psB)      = w0;
        *(uint4*)(psB + 16) = w1;
    }
    __syncthreads();

    for (int kb = 0; kb < nk; kb++) {
        uint4 pa0, pa1, pw0, pw1;
        const bool more = (kb + 1) < nk;
        if (more) {
            const __half* An = Ap + (kb + 1) * 32;
            const __half* Wn = Wp + (kb + 1) * 32;
            pa0 = *(const uint4*)(An);
            pa1 = *(const uint4*)(An + 8);
            pw0 = *(const uint4*)(Wn);
            pw1 = *(const uint4*)(Wn + 8);
        }

        const uint32_t aBase = smb + (kb & 1) * STAGEB;
        const uint32_t bBase = aBase + 2 * STAGEB;
        #pragma unroll
        for (int ks = 0; ks < 2; ks++) {
            uint32_t af[2][4];
            uint32_t bf[8][2];
            #pragma unroll
            for (int mt = 0; mt < 2; mt++)
                ldm_x4(af[mt], aBase + offA0 + (uint32_t)(mt * 16 * ROWB + ks * 32));
            #pragma unroll
            for (int ntp = 0; ntp < 4; ntp++) {
                uint32_t bq[4];
                ldm_x4(bq, bBase + offB0 + (uint32_t)(ntp * 16 * ROWB + ks * 32));
                bf[2 * ntp][0]     = bq[0];
                bf[2 * ntp][1]     = bq[1];
                bf[2 * ntp + 1][0] = bq[2];
                bf[2 * ntp + 1][1] = bq[3];
            }
            #pragma unroll
            for (int mt = 0; mt < 2; mt++)
                #pragma unroll
                for (int nt = 0; nt < 8; nt++)
                    mma_f16(acc[mt][nt], af[mt], bf[nt]);
        }

        if (more) {
            char* dst_a = sm + ((kb + 1) & 1) * STAGEB + lrow * ROWB + lks * 32;
            char* dst_b = dst_a + 2 * STAGEB;
            *(uint4*)(dst_a)      = pa0;
            *(uint4*)(dst_a + 16) = pa1;
            *(uint4*)(dst_b)      = pw0;
            *(uint4*)(dst_b + 16) = pw1;
        }
        __syncthreads();
    }

    #pragma unroll
    for (int mt = 0; mt < 2; mt++) {
        #pragma unroll
        for (int half = 0; half < 2; half++) {
            const int r = blockIdx.y * 128 + warpM + mt * 16 + g + half * 8;
            if (r >= M) continue;
            const size_t off = (size_t)r * Nout;
            #pragma unroll
            for (int nt = 0; nt < 8; nt++) {
                const int c = blockIdx.x * 128 + warpN + nt * 8 + q * 2;
                epi_store(Cout, off, c, acc[mt][nt][half * 2 + 0], acc[mt][nt][half * 2 + 1],
                          bias, Res, epi, cvtout);
            }
        }
    }
}

// ---------------- FP16 GEMM, 64x128 tile, 8 warps of 32x32 (N=768 GEMMs) ----
// Same BK=32 / ldmatrix / register-prefetch / one-barrier structure as
// gemm_tc; 2x the blocks for small grids (132 -> 264 on 148 SMs) and
// ~30 KB smem + smaller acc -> 3-4 blocks/SM.
constexpr int ASTG64 = 64 * ROWB;        // 5120 B A stage
constexpr int BSTG64 = 128 * ROWB;       // 10240 B B stage
// layout: A0 @0, A1 @ASTG64, B0 @2*ASTG64, B1 @2*ASTG64+BSTG64

__global__ __launch_bounds__(256) void gemm_tc64(const __half* __restrict__ A,
                                                 const __half* __restrict__ W,
                                                 const float* __restrict__ bias,
                                                 const float* __restrict__ Res,
                                                 void* __restrict__ Cout,
                                                 int M, int K, int Nout, int epi, int cvtout)
{
    __shared__ __align__(16) char sm[2 * ASTG64 + 2 * BSTG64];
    const uint32_t smb = (uint32_t)__cvta_generic_to_shared(sm);

    const int t = threadIdx.x;
    const int warp = t >> 5, lane = t & 31;
    const int g = lane >> 2, q = lane & 3;
    const int warpM = (warp >> 2) * 32;      // 0 or 32
    const int warpN = (warp & 3) * 32;       // 0,32,64,96

    // ---- producers ----
    // A: 64 rows x 4 chunks(16B); thread t -> row t>>2, chunk t&3.
    const int arow = t >> 2, achk = t & 3;
    int rowA = blockIdx.y * 64 + arow;
    if (rowA >= M) rowA = M - 1;
    const __half* Ap = A + (size_t)rowA * K + achk * 8;
    char* const psA = sm + arow * ROWB + achk * 16;
    // B: 128 rows x 4 chunks; thread t -> row t>>1, chunks 2*(t&1), 2*(t&1)+1.
    const int brow = t >> 1, bhlf = t & 1;
    const __half* Wp = W + (size_t)(blockIdx.x * 128 + brow) * K + bhlf * 16;
    char* const psB = sm + 2 * ASTG64 + brow * ROWB + bhlf * 32;

    const uint32_t offA0 = (uint32_t)((warpM + (lane & 15)) * ROWB + (lane >> 4) * 16);
    const uint32_t offB0 = (uint32_t)((warpN + (lane & 7) + ((lane >> 4) << 3)) * ROWB
                                      + ((lane >> 3) & 1) * 16);

    float acc[2][4][4];
    #pragma unroll
    for (int mt = 0; mt < 2; mt++)
        #pragma unroll
        for (int nt = 0; nt < 4; nt++)
            #pragma unroll
            for (int i = 0; i < 4; i++) acc[mt][nt][i] = 0.f;

    const int nk = K >> 5;

    // prologue
    {
        *(uint4*)(psA)      = *(const uint4*)(Ap);
        *(uint4*)(psB)      = *(const uint4*)(Wp);
        *(uint4*)(psB + 16) = *(const uint4*)(Wp + 8);
    }
    __syncthreads();

    for (int kb = 0; kb < nk; kb++) {
        uint4 pa, pw0, pw1;
        const bool more = (kb + 1) < nk;
        if (more) {
            pa  = *(const uint4*)(Ap + (kb + 1) * 32);
            pw0 = *(const uint4*)(Wp + (kb + 1) * 32);
            pw1 = *(const uint4*)(Wp + (kb + 1) * 32 + 8);
        }

        const uint32_t aBase = smb + (kb & 1) * ASTG64;
        const uint32_t bBase = smb + 2 * ASTG64 + (kb & 1) * BSTG64;
        #pragma unroll
        for (int ks = 0; ks < 2; ks++) {
            uint32_t af[2][4];
            uint32_t bf[4][2];
            #pragma unroll
            for (int mt = 0; mt < 2; mt++)
                ldm_x4(af[mt], aBase + offA0 + (uint32_t)(mt * 16 * ROWB + ks * 32));
            #pragma unroll
            for (int ntp = 0; ntp < 2; ntp++) {
                uint32_t bq[4];
                ldm_x4(bq, bBase + offB0 + (uint32_t)(ntp * 16 * ROWB + ks * 32));
                bf[2 * ntp][0]     = bq[0];
                bf[2 * ntp][1]     = bq[1];
                bf[2 * ntp + 1][0] = bq[2];
                bf[2 * ntp + 1][1] = bq[3];
            }
            #pragma unroll
            for (int mt = 0; mt < 2; mt++)
                #pragma unroll
                for (int nt = 0; nt < 4; nt++)
                    mma_f16(acc[mt][nt], af[mt], bf[nt]);
        }

        if (more) {
            char* da = sm + ((kb + 1) & 1) * ASTG64 + arow * ROWB + achk * 16;
            char* db = sm + 2 * ASTG64 + ((kb + 1) & 1) * BSTG64 + brow * ROWB + bhlf * 32;
            *(uint4*)(da)      = pa;
            *(uint4*)(db)      = pw0;
            *(uint4*)(db + 16) = pw1;
        }
        __syncthreads();
    }

    #pragma unroll
    for (int mt = 0; mt < 2; mt++) {
        #pragma unroll
        for (int half = 0; half < 2; half++) {
            const int r = blockIdx.y * 64 + warpM + mt * 16 + g + half * 8;
            if (r >= M) continue;
            const size_t off = (size_t)r * Nout;
            #pragma unroll
            for (int nt = 0; nt < 4; nt++) {
                const int c = blockIdx.x * 128 + warpN + nt * 8 + q * 2;
                epi_store(Cout, off, c, acc[mt][nt][half * 2 + 0], acc[mt][nt][half * 2 + 1],
                          bias, Res, epi, cvtout);
            }
        }
    }
}

// ---------------- fused block-diagonal attention (fp32 in, fp16 out) --------
constexpr int ATTN_SMEM = (SEQ * DH * 2 + 8 * SEQ + 8 * DH) * 4;

__global__ __launch_bounds__(256) void attn_kernel(const float* __restrict__ QKV,
                                                   __half* __restrict__ Out)
{
    extern __shared__ float smf[];
    float* Kt = smf;
    float* Vs = Kt + DH * SEQ;
    float* Sb = Vs + SEQ * DH;
    float* Qb = Sb + 8 * SEQ;

    int bh = blockIdx.x;
    int b = bh / HEADS, h = bh % HEADS;
    int base = b * SEQ;
    int qoff = h * DH, koff = E + h * DH, voff = 2 * E + h * DH;

    for (int idx = threadIdx.x; idx < SEQ * DH; idx += 256) {
        int j = idx >> 6, d = idx & 63;
        size_t rb = (size_t)(base + j) * E3;
        Kt[d * SEQ + j] = QKV[rb + koff + d];
        Vs[idx]         = QKV[rb + voff + d];
    }
    __syncthreads();

    int w = threadIdx.x >> 5, lane = threadIdx.x & 31;
    float* S = Sb + w * SEQ;
    float* Q = Qb + w * DH;

    for (int i = w; i < SEQ; i += 8) {
        const float* qp = QKV + (size_t)(base + i) * E3 + qoff;
        Q[lane]      = qp[lane];
        Q[lane + 32] = qp[lane + 32];
        __syncwarp();

        float sv[6];
        #pragma unroll
        for (int jj = 0; jj < 6; jj++) sv[jj] = 0.f;
        #pragma unroll 8
        for (int d = 0; d < DH; d++) {
            float qd = Q[d];
            const float* kr = Kt + d * SEQ;
            #pragma unroll
            for (int jj = 0; jj < 6; jj++)
                sv[jj] = fmaf(qd, kr[jj * 32 + lane], sv[jj]);
        }

        float mx = -3.0e38f;
        #pragma unroll
        for (int jj = 0; jj < 6; jj++) {
            int j = jj * 32 + lane;
            if (j < SEQ) { sv[jj] *= 0.125f; mx = fmaxf(mx, sv[jj]); }
        }
        #pragma unroll
        for (int o = 16; o; o >>= 1) mx = fmaxf(mx, __shfl_xor_sync(~0u, mx, o));

        float sum = 0.f;
        #pragma unroll
        for (int jj = 0; jj < 6; jj++) {
            int j = jj * 32 + lane;
            if (j < SEQ) { float e = __expf(sv[jj] - mx); S[j] = e; sum += e; }
        }
        #pragma unroll
        for (int o = 16; o; o >>= 1) sum += __shfl_xor_sync(~0u, sum, o);
        float inv = 1.0f / sum;
        __syncwarp();

        float o0 = 0.f, o1 = 0.f;
        for (int j = 0; j < SEQ; j++) {
            float p = S[j];
            o0 = fmaf(p, Vs[j * 64 + lane],      o0);
            o1 = fmaf(p, Vs[j * 64 + lane + 32], o1);
        }
        __half* op = Out + (size_t)(base + i) * E + qoff;
        op[lane]      = __float2half_rn(o0 * inv);
        op[lane + 32] = __float2half_rn(o1 * inv);
        __syncwarp();
    }
}

__global__ void fill_ones_kernel(float* p, int n)
{
    int i = blockIdx.x * blockDim.x + threadIdx.x;
    if (i < n) p[i] = 1.0f;
}

// ---------------- host orchestration ----------------
extern "C" void kernel_launch(void* const* d_in, const int* in_sizes, int n_in,
                              void* d_out, int out_size)
{
    const float* pixel   = (const float*)d_in[0];
    const float* patch_W = (const float*)d_in[1];
    const float* patch_b = (const float*)d_in[2];
    const float* row_emb = (const float*)d_in[3];
    const float* col_emb = (const float*)d_in[4];
    const float* cls     = (const float*)d_in[5];
    const float* ln1_g   = (const float*)d_in[6];
    const float* ln1_b   = (const float*)d_in[7];
    const float* in_w    = (const float*)d_in[8];
    const float* in_b    = (const float*)d_in[9];
    const float* out_w   = (const float*)d_in[10];
    const float* out_b   = (const float*)d_in[11];
    const float* ln2_g   = (const float*)d_in[12];
    const float* ln2_b   = (const float*)d_in[13];
    const float* mlp_w1  = (const float*)d_in[14];
    const float* mlp_b1  = (const float*)d_in[15];
    const float* mlp_w2  = (const float*)d_in[16];
    const float* mlp_b2  = (const float*)d_in[17];
    const float* fin_g   = (const float*)d_in[18];
    const float* fin_b   = (const float*)d_in[19];
    const float* br_w1   = (const float*)d_in[20];
    const float* br_b1   = (const float*)d_in[21];
    const float* br_w2   = (const float*)d_in[22];
    const float* br_b2   = (const float*)d_in[23];
    const float* br_g    = (const float*)d_in[24];
    const float* br_b    = (const float*)d_in[25];

    float *X, *QKV, *PE, *OUTP;
    __half *XN, *O, *H1, *PT;
    __half *Wpatch, *Win, *Wout, *Wm1, *Wm2, *Wb1, *Wb2;
    cudaGetSymbolAddress((void**)&X,    g_X);
    cudaGetSymbolAddress((void**)&XN,   g_XN);
    cudaGetSymbolAddress((void**)&QKV,  g_QKV);
    cudaGetSymbolAddress((void**)&O,    g_O);
    cudaGetSymbolAddress((void**)&H1,   g_H1);
    cudaGetSymbolAddress((void**)&PT,   g_PT);
    cudaGetSymbolAddress((void**)&PE,   g_PE);
    cudaGetSymbolAddress((void**)&OUTP, g_OUTP);
    cudaGetSymbolAddress((void**)&Wpatch, g_Wpatch);
    cudaGetSymbolAddress((void**)&Win,    g_Win);
    cudaGetSymbolAddress((void**)&Wout,   g_Wout);
    cudaGetSymbolAddress((void**)&Wm1,    g_Wm1);
    cudaGetSymbolAddress((void**)&Wm2,    g_Wm2);
    cudaGetSymbolAddress((void**)&Wb1,    g_Wb1);
    cudaGetSymbolAddress((void**)&Wb2,    g_Wb2);

    cudaFuncSetAttribute(attn_kernel, cudaFuncAttributeMaxDynamicSharedMemorySize, ATTN_SMEM);

    const int MPAT = Bn * NPAT;
    const dim3 blk(256);

    // ---- weight conversion (replayed each graph launch; ~100us) ----
    auto cvt = [&](const float* s, __half* d, int n) {
        cvt_kernel<<<(n / 8 + 255) / 256, blk>>>(s, d, n / 8);
    };
    cvt(patch_W, Wpatch, 768 * 768);
    cvt(in_w,    Win,    12 * 2304 * 768);
    cvt(out_w,   Wout,   12 * 768 * 768);
    cvt(mlp_w1,  Wm1,    12 * 3072 * 768);
    cvt(mlp_w2,  Wm2,    12 * 768 * 3072);
    cvt(br_w1,   Wb1,    1536 * 768);
    cvt(br_w2,   Wb2,    2048 * 1536);

    // ---- patch embedding (N=768 -> 64-row tiles, MPAT=2688=42*64) ----
    patchify_kernel<<<(MPAT * E + 255) / 256, blk>>>(pixel, PT);
    gemm_tc64<<<dim3(E / 128, MPAT / 64), blk>>>(PT, Wpatch, patch_b, nullptr, PE,
                                                 MPAT, E, E, 0, 0);
    assemble_kernel<<<(Nrow * E + 255) / 256, blk>>>(PE, cls, row_emb, col_emb, X);

    const int GY   = (Nrow + 127) / 128;   // 22
    const int GY64 = (Nrow + 63) / 64;     // 43

    for (int l = 0; l < Ll; l++) {
        ln_kernel<<<Nrow, blk>>>(X, ln1_g + l * E, ln1_b + l * E, XN, E, 1);
        gemm_tc<<<dim3(E3 / 128, GY), blk>>>(XN, Win + (size_t)l * E3 * E, in_b + (size_t)l * E3,
                                             nullptr, QKV, Nrow, E, E3, 0, 0);
        attn_kernel<<<Bn * HEADS, blk, ATTN_SMEM>>>(QKV, O);
        gemm_tc64<<<dim3(E / 128, GY64), blk>>>(O, Wout + (size_t)l * E * E, out_b + (size_t)l * E,
                                                X, X, Nrow, E, E, 2, 0);
        ln_kernel<<<Nrow, blk>>>(X, ln2_g + l * E, ln2_b + l * E, XN, E, 1);
        gemm_tc<<<dim3(MLPD / 128, GY), blk>>>(XN, Wm1 + (size_t)l * MLPD * E, mlp_b1 + (size_t)l * MLPD,
                                               nullptr, H1, Nrow, E, MLPD, 1, 1);
        gemm_tc64<<<dim3(E / 128, GY64), blk>>>(H1, Wm2 + (size_t)l * E * MLPD, mlp_b2 + (size_t)l * E,
                                                X, X, Nrow, MLPD, E, 2, 0);
    }

    ln_kernel<<<Nrow, blk>>>(X, fin_g, fin_b, XN, E, 1);
    gemm_tc<<<dim3(E2 / 128, GY), blk>>>(XN, Wb1, br_b1, nullptr, H1, Nrow, E, E2, 1, 1);
    gemm_tc<<<dim3(OUTD / 128, GY), blk>>>(H1, Wb2, br_b2, nullptr, OUTP, Nrow, E2, OUTD, 0, 0);
    ln_kernel<<<Nrow, blk>>>(OUTP, br_g, br_b, (float*)d_out, OUTD, 0);

    long long mainN = (long long)Nrow * OUTD;
    if ((long long)out_size > mainN) {
        int extra = (int)((long long)out_size - mainN);
        fill_ones_kernel<<<(extra + 255) / 256, blk>>>((float*)d_out + mainN, extra);
    }
}

// round 17
// speedup vs baseline: 1.0523x; 1.0523x over previous
#include <cuda_runtime.h>
#include <cuda_fp16.h>
#include <math.h>
#include <stdint.h>

// ---------------- problem constants ----------------
namespace {
constexpr int Bn    = 16;
constexpr int E     = 768;
constexpr int HEADS = 12;
constexpr int Ll    = 12;
constexpr int MLPD  = 3072;
constexpr int OUTD  = 2048;
constexpr int PW    = 42;
constexpr int NPAT  = 168;
constexpr int SEQ   = 169;
constexpr int Nrow  = 2704;
constexpr int DH    = 64;
constexpr int E3    = 2304;
constexpr int E2    = 1536;
constexpr int PERSIST = 296;   // 148 SMs x 2 blocks
}

// ---------------- scratch (static device globals) ----------------
__device__ __align__(16) float  g_X   [Nrow * E];
__device__ __align__(16) __half g_XN  [Nrow * E];
__device__ __align__(16) float  g_QKV [Nrow * E3];
__device__ __align__(16) __half g_O   [Nrow * E];
__device__ __align__(16) __half g_H1  [Nrow * MLPD];
__device__ __align__(16) __half g_PT  [Bn * NPAT * E];
__device__ __align__(16) float  g_PE  [Bn * NPAT * E];
__device__ __align__(16) float  g_OUTP[Nrow * OUTD];

// pre-converted fp16 weights
__device__ __align__(16) __half g_Wpatch[768 * 768];
__device__ __align__(16) __half g_Win   [12 * 2304 * 768];
__device__ __align__(16) __half g_Wout  [12 * 768 * 768];
__device__ __align__(16) __half g_Wm1   [12 * 3072 * 768];
__device__ __align__(16) __half g_Wm2   [12 * 768 * 3072];
__device__ __align__(16) __half g_Wb1   [1536 * 768];
__device__ __align__(16) __half g_Wb2   [2048 * 1536];

// ---------------- fp16 helpers ----------------
__device__ __forceinline__ uint32_t f2h2(float a, float b)
{
    __half2 h = __halves2half2(__float2half_rn(a), __float2half_rn(b));
    return *(uint32_t*)&h;
}

__device__ __forceinline__ void mma_f16(float* c, const uint32_t* a, const uint32_t* b)
{
    asm volatile(
        "mma.sync.aligned.m16n8k16.row.col.f32.f16.f16.f32 "
        "{%0,%1,%2,%3}, {%4,%5,%6,%7}, {%8,%9}, {%0,%1,%2,%3};\n"
        : "+f"(c[0]), "+f"(c[1]), "+f"(c[2]), "+f"(c[3])
        : "r"(a[0]), "r"(a[1]), "r"(a[2]), "r"(a[3]), "r"(b[0]), "r"(b[1]));
}

__device__ __forceinline__ void ldm_x4(uint32_t* r, uint32_t saddr)
{
    asm volatile("ldmatrix.sync.aligned.m8n8.x4.shared.b16 {%0,%1,%2,%3}, [%4];"
                 : "=r"(r[0]), "=r"(r[1]), "=r"(r[2]), "=r"(r[3]) : "r"(saddr));
}

// ---------------- weight conversion (8 floats -> 8 halves per thread) -------
__global__ void cvt_kernel(const float* __restrict__ src, __half* __restrict__ dst, int n8)
{
    int i = blockIdx.x * blockDim.x + threadIdx.x;
    if (i >= n8) return;
    float4 v0 = ((const float4*)src)[2 * i];
    float4 v1 = ((const float4*)src)[2 * i + 1];
    uint4 o;
    o.x = f2h2(v0.x, v0.y);
    o.y = f2h2(v0.z, v0.w);
    o.z = f2h2(v1.x, v1.y);
    o.w = f2h2(v1.z, v1.w);
    ((uint4*)dst)[i] = o;
}

// ---------------- patchify (writes fp16) ----------------
__global__ void patchify_kernel(const float* __restrict__ px, __half* __restrict__ PT)
{
    int idx = blockIdx.x * blockDim.x + threadIdx.x;
    if (idx >= Bn * NPAT * E) return;
    int k = idx % E;
    int m = idx / E;
    int b = m / NPAT, p = m % NPAT;
    int ph = p / PW, pw = p % PW;
    int c  = k >> 8;
    int r  = k & 255;
    int ii = r >> 4, jj = r & 15;
    PT[idx] = __float2half_rn(px[(((size_t)(b * 3 + c) * 64 + ph * 16 + ii) * 672) + pw * 16 + jj]);
}

// ---------------- assemble ----------------
__global__ void assemble_kernel(const float* __restrict__ PE_, const float* __restrict__ cls,
                                const float* __restrict__ row_emb, const float* __restrict__ col_emb,
                                float* __restrict__ X)
{
    int idx = blockIdx.x * blockDim.x + threadIdx.x;
    if (idx >= Nrow * E) return;
    int e = idx % E;
    int n = idx / E;
    int b = n / SEQ, s = n % SEQ;
    float v;
    if (s == 0) {
        v = cls[e];
    } else {
        int p = s - 1, ph = p / PW, pw = p % PW;
        float pos = (e < 384) ? row_emb[ph * 384 + e] : col_emb[pw * 384 + (e - 384)];
        v = PE_[((size_t)(b * NPAT) + p) * E + e] + pos;
    }
    X[idx] = v;
}

// ---------------- LayerNorm (float4-vectorized; optional fp16 output) -------
__global__ void ln_kernel(const float* __restrict__ x, const float* __restrict__ g,
                          const float* __restrict__ b, void* __restrict__ y, int D, int cvtout)
{
    int row = blockIdx.x;
    const float4* xr = (const float4*)(x + (size_t)row * D);
    const int D4 = D >> 2;
    float s = 0.f, s2 = 0.f;
    for (int i = threadIdx.x; i < D4; i += blockDim.x) {
        float4 v = xr[i];
        s  += v.x + v.y + v.z + v.w;
        s2 += v.x * v.x + v.y * v.y + v.z * v.z + v.w * v.w;
    }
    __shared__ float shs[8], shs2[8];
    #pragma unroll
    for (int o = 16; o; o >>= 1) {
        s  += __shfl_xor_sync(~0u, s,  o);
        s2 += __shfl_xor_sync(~0u, s2, o);
    }
    int w = threadIdx.x >> 5, lane = threadIdx.x & 31;
    const int nw = blockDim.x >> 5;
    if (lane == 0) { shs[w] = s; shs2[w] = s2; }
    __syncthreads();
    if (w == 0) {
        s  = lane < nw ? shs[lane]  : 0.f;
        s2 = lane < nw ? shs2[lane] : 0.f;
        #pragma unroll
        for (int o = 4; o; o >>= 1) {
            s  += __shfl_xor_sync(~0u, s,  o);
            s2 += __shfl_xor_sync(~0u, s2, o);
        }
        if (lane == 0) { shs[0] = s; shs2[0] = s2; }
    }
    __syncthreads();
    float m   = shs[0] / (float)D;
    float var = shs2[0] / (float)D - m * m;
    float inv = rsqrtf(var + 1e-5f);
    const float4* gp = (const float4*)g;
    const float4* bp = (const float4*)b;
    if (cvtout) {
        uint2* yr = (uint2*)((__half*)y + (size_t)row * D);
        for (int i = threadIdx.x; i < D4; i += blockDim.x) {
            float4 v = xr[i], gg = gp[i], bb = bp[i];
            uint2 o;
            o.x = f2h2((v.x - m) * inv * gg.x + bb.x, (v.y - m) * inv * gg.y + bb.y);
            o.y = f2h2((v.z - m) * inv * gg.z + bb.z, (v.w - m) * inv * gg.w + bb.w);
            yr[i] = o;
        }
    } else {
        float4* yr = (float4*)((float*)y + (size_t)row * D);
        for (int i = threadIdx.x; i < D4; i += blockDim.x) {
            float4 v = xr[i], gg = gp[i], bb = bp[i];
            float4 o;
            o.x = (v.x - m) * inv * gg.x + bb.x;
            o.y = (v.y - m) * inv * gg.y + bb.y;
            o.z = (v.z - m) * inv * gg.z + bb.z;
            o.w = (v.w - m) * inv * gg.w + bb.w;
            yr[i] = o;
        }
    }
}

// ---------------- GEMM epilogue helper ----------------
__device__ __forceinline__ void epi_store(void* Cout, size_t off, int c,
                                          float v0, float v1,
                                          const float* bias, const float* Res,
                                          int epi, int cvtout)
{
    v0 += bias[c];
    v1 += bias[c + 1];
    if (epi == 1) {
        v0 = 0.5f * v0 * (1.0f + erff(v0 * 0.70710678118654752f));
        v1 = 0.5f * v1 * (1.0f + erff(v1 * 0.70710678118654752f));
    } else if (epi == 2) {
        v0 += Res[off + c];
        v1 += Res[off + c + 1];
    }
    if (cvtout) {
        *(uint32_t*)((__half*)Cout + off + c) = f2h2(v0, v1);
    } else {
        *(float2*)((float*)Cout + off + c) = make_float2(v0, v1);
    }
}

// ---------------- FP16 GEMM, 128x128 tile, BK=32, ldmatrix, PERSISTENT ------
// Round-14 proven internals (256 threads = 8 warps of 32x64, register
// prefetch -> ldmatrix/MMA -> STS -> ONE barrier per slab; ROWB=80 layout).
// ROUND-17 CHANGE: persistent-tile wrapper. grid = min(ntiles, 296); each
// block loops tile += gridDim.x, removing wave-quantization tails.
// Safe: nk is even for all K here (24/48/96), so the next tile's stage-0
// prologue never collides with the last-read stage-1 buffer; epilogue reads
// only registers.
constexpr int ROWB   = 80;               // bytes per smem row (64 data + 16 pad)
constexpr int STAGEB = 128 * ROWB;       // 10240 B per stage

__global__ __launch_bounds__(256) void gemm_tc(const __half* __restrict__ A,
                                               const __half* __restrict__ W,
                                               const float* __restrict__ bias,
                                               const float* __restrict__ Res,
                                               void* __restrict__ Cout,
                                               int M, int K, int Nout, int epi, int cvtout)
{
    __shared__ __align__(16) char sm[4 * STAGEB];
    const uint32_t smb = (uint32_t)__cvta_generic_to_shared(sm);

    const int t = threadIdx.x;
    const int warp = t >> 5, lane = t & 31;
    const int g = lane >> 2, q = lane & 3;
    const int warpM = (warp >> 1) * 32;
    const int warpN = (warp & 1) * 64;

    const int lrow = t >> 1;
    const int lks  = t & 1;
    const uint32_t offA0 = (uint32_t)((warpM + (lane & 15)) * ROWB + (lane >> 4) * 16);
    const uint32_t offB0 = (uint32_t)((warpN + (lane & 7) + ((lane >> 4) << 3)) * ROWB
                                      + ((lane >> 3) & 1) * 16);
    char* const psA = sm + lrow * ROWB + lks * 32;
    char* const psB = psA + 2 * STAGEB;

    const int gx = Nout >> 7;
    const int ntiles = gx * ((M + 127) >> 7);
    const int nk = K >> 5;

    for (int tile = blockIdx.x; tile < ntiles; tile += gridDim.x) {
        const int bx = tile % gx;
        const int by = tile / gx;

        int rowA = by * 128 + lrow;
        if (rowA >= M) rowA = M - 1;
        const __half* Ap = A + (size_t)rowA * K + lks * 16;
        const __half* Wp = W + (size_t)(bx * 128 + lrow) * K + lks * 16;

        float acc[2][8][4];
        #pragma unroll
        for (int mt = 0; mt < 2; mt++)
            #pragma unroll
            for (int nt = 0; nt < 8; nt++)
                #pragma unroll
                for (int i = 0; i < 4; i++) acc[mt][nt][i] = 0.f;

        // prologue: stage 0
        {
            uint4 a0 = *(const uint4*)(Ap);
            uint4 a1 = *(const uint4*)(Ap + 8);
            uint4 w0 = *(const uint4*)(Wp);
            uint4 w1 = *(const uint4*)(Wp + 8);
            *(uint4*)(psA)      = a0;
            *(uint4*)(psA + 16) = a1;
            *(uint4*)(psB)      = w0;
            *(uint4*)(psB + 16) = w1;
        }
        __syncthreads();

        for (int kb = 0; kb < nk; kb++) {
            uint4 pa0, pa1, pw0, pw1;
            const bool more = (kb + 1) < nk;
            if (more) {
                const __half* An = Ap + (kb + 1) * 32;
                const __half* Wn = Wp + (kb + 1) * 32;
                pa0 = *(const uint4*)(An);
                pa1 = *(const uint4*)(An + 8);
                pw0 = *(const uint4*)(Wn);
                pw1 = *(const uint4*)(Wn + 8);
            }

            const uint32_t aBase = smb + (kb & 1) * STAGEB;
            const uint32_t bBase = aBase + 2 * STAGEB;
            #pragma unroll
            for (int ks = 0; ks < 2; ks++) {
                uint32_t af[2][4];
                uint32_t bf[8][2];
                #pragma unroll
                for (int mt = 0; mt < 2; mt++)
                    ldm_x4(af[mt], aBase + offA0 + (uint32_t)(mt * 16 * ROWB + ks * 32));
                #pragma unroll
                for (int ntp = 0; ntp < 4; ntp++) {
                    uint32_t bq[4];
                    ldm_x4(bq, bBase + offB0 + (uint32_t)(ntp * 16 * ROWB + ks * 32));
                    bf[2 * ntp][0]     = bq[0];
                    bf[2 * ntp][1]     = bq[1];
                    bf[2 * ntp + 1][0] = bq[2];
                    bf[2 * ntp + 1][1] = bq[3];
                }
                #pragma unroll
                for (int mt = 0; mt < 2; mt++)
                    #pragma unroll
                    for (int nt = 0; nt < 8; nt++)
                        mma_f16(acc[mt][nt], af[mt], bf[nt]);
            }

            if (more) {
                char* dst_a = sm + ((kb + 1) & 1) * STAGEB + lrow * ROWB + lks * 32;
                char* dst_b = dst_a + 2 * STAGEB;
                *(uint4*)(dst_a)      = pa0;
                *(uint4*)(dst_a + 16) = pa1;
                *(uint4*)(dst_b)      = pw0;
                *(uint4*)(dst_b + 16) = pw1;
            }
            __syncthreads();
        }

        // epilogue
        #pragma unroll
        for (int mt = 0; mt < 2; mt++) {
            #pragma unroll
            for (int half = 0; half < 2; half++) {
                const int r = by * 128 + warpM + mt * 16 + g + half * 8;
                if (r >= M) continue;
                const size_t off = (size_t)r * Nout;
                #pragma unroll
                for (int nt = 0; nt < 8; nt++) {
                    const int c = bx * 128 + warpN + nt * 8 + q * 2;
                    epi_store(Cout, off, c, acc[mt][nt][half * 2 + 0], acc[mt][nt][half * 2 + 1],
                              bias, Res, epi, cvtout);
                }
            }
        }
    }
}

// ---------------- fused block-diagonal attention (fp32 in, fp16 out) --------
constexpr int ATTN_SMEM = (SEQ * DH * 2 + 8 * SEQ + 8 * DH) * 4;

__global__ __launch_bounds__(256) void attn_kernel(const float* __restrict__ QKV,
                                                   __half* __restrict__ Out)
{
    extern __shared__ float smf[];
    float* Kt = smf;
    float* Vs = Kt + DH * SEQ;
    float* Sb = Vs + SEQ * DH;
    float* Qb = Sb + 8 * SEQ;

    int bh = blockIdx.x;
    int b = bh / HEADS, h = bh % HEADS;
    int base = b * SEQ;
    int qoff = h * DH, koff = E + h * DH, voff = 2 * E + h * DH;

    for (int idx = threadIdx.x; idx < SEQ * DH; idx += 256) {
        int j = idx >> 6, d = idx & 63;
        size_t rb = (size_t)(base + j) * E3;
        Kt[d * SEQ + j] = QKV[rb + koff + d];
        Vs[idx]         = QKV[rb + voff + d];
    }
    __syncthreads();

    int w = threadIdx.x >> 5, lane = threadIdx.x & 31;
    float* S = Sb + w * SEQ;
    float* Q = Qb + w * DH;

    for (int i = w; i < SEQ; i += 8) {
        const float* qp = QKV + (size_t)(base + i) * E3 + qoff;
        Q[lane]      = qp[lane];
        Q[lane + 32] = qp[lane + 32];
        __syncwarp();

        float sv[6];
        #pragma unroll
        for (int jj = 0; jj < 6; jj++) sv[jj] = 0.f;
        #pragma unroll 8
        for (int d = 0; d < DH; d++) {
            float qd = Q[d];
            const float* kr = Kt + d * SEQ;
            #pragma unroll
            for (int jj = 0; jj < 6; jj++)
                sv[jj] = fmaf(qd, kr[jj * 32 + lane], sv[jj]);
        }

        float mx = -3.0e38f;
        #pragma unroll
        for (int jj = 0; jj < 6; jj++) {
            int j = jj * 32 + lane;
            if (j < SEQ) { sv[jj] *= 0.125f; mx = fmaxf(mx, sv[jj]); }
        }
        #pragma unroll
        for (int o = 16; o; o >>= 1) mx = fmaxf(mx, __shfl_xor_sync(~0u, mx, o));

        float sum = 0.f;
        #pragma unroll
        for (int jj = 0; jj < 6; jj++) {
            int j = jj * 32 + lane;
            if (j < SEQ) { float e = __expf(sv[jj] - mx); S[j] = e; sum += e; }
        }
        #pragma unroll
        for (int o = 16; o; o >>= 1) sum += __shfl_xor_sync(~0u, sum, o);
        float inv = 1.0f / sum;
        __syncwarp();

        float o0 = 0.f, o1 = 0.f;
        for (int j = 0; j < SEQ; j++) {
            float p = S[j];
            o0 = fmaf(p, Vs[j * 64 + lane],      o0);
            o1 = fmaf(p, Vs[j * 64 + lane + 32], o1);
        }
        __half* op = Out + (size_t)(base + i) * E + qoff;
        op[lane]      = __float2half_rn(o0 * inv);
        op[lane + 32] = __float2half_rn(o1 * inv);
        __syncwarp();
    }
}

__global__ void fill_ones_kernel(float* p, int n)
{
    int i = blockIdx.x * blockDim.x + threadIdx.x;
    if (i < n) p[i] = 1.0f;
}

// ---------------- host orchestration ----------------
static inline int pgrid(int M, int Nout)
{
    int nt = (Nout >> 7) * ((M + 127) >> 7);
    return nt < PERSIST ? nt : PERSIST;
}

extern "C" void kernel_launch(void* const* d_in, const int* in_sizes, int n_in,
                              void* d_out, int out_size)
{
    const float* pixel   = (const float*)d_in[0];
    const float* patch_W = (const float*)d_in[1];
    const float* patch_b = (const float*)d_in[2];
    const float* row_emb = (const float*)d_in[3];
    const float* col_emb = (const float*)d_in[4];
    const float* cls     = (const float*)d_in[5];
    const float* ln1_g   = (const float*)d_in[6];
    const float* ln1_b   = (const float*)d_in[7];
    const float* in_w    = (const float*)d_in[8];
    const float* in_b    = (const float*)d_in[9];
    const float* out_w   = (const float*)d_in[10];
    const float* out_b   = (const float*)d_in[11];
    const float* ln2_g   = (const float*)d_in[12];
    const float* ln2_b   = (const float*)d_in[13];
    const float* mlp_w1  = (const float*)d_in[14];
    const float* mlp_b1  = (const float*)d_in[15];
    const float* mlp_w2  = (const float*)d_in[16];
    const float* mlp_b2  = (const float*)d_in[17];
    const float* fin_g   = (const float*)d_in[18];
    const float* fin_b   = (const float*)d_in[19];
    const float* br_w1   = (const float*)d_in[20];
    const float* br_b1   = (const float*)d_in[21];
    const float* br_w2   = (const float*)d_in[22];
    const float* br_b2   = (const float*)d_in[23];
    const float* br_g    = (const float*)d_in[24];
    const float* br_b    = (const float*)d_in[25];

    float *X, *QKV, *PE, *OUTP;
    __half *XN, *O, *H1, *PT;
    __half *Wpatch, *Win, *Wout, *Wm1, *Wm2, *Wb1, *Wb2;
    cudaGetSymbolAddress((void**)&X,    g_X);
    cudaGetSymbolAddress((void**)&XN,   g_XN);
    cudaGetSymbolAddress((void**)&QKV,  g_QKV);
    cudaGetSymbolAddress((void**)&O,    g_O);
    cudaGetSymbolAddress((void**)&H1,   g_H1);
    cudaGetSymbolAddress((void**)&PT,   g_PT);
    cudaGetSymbolAddress((void**)&PE,   g_PE);
    cudaGetSymbolAddress((void**)&OUTP, g_OUTP);
    cudaGetSymbolAddress((void**)&Wpatch, g_Wpatch);
    cudaGetSymbolAddress((void**)&Win,    g_Win);
    cudaGetSymbolAddress((void**)&Wout,   g_Wout);
    cudaGetSymbolAddress((void**)&Wm1,    g_Wm1);
    cudaGetSymbolAddress((void**)&Wm2,    g_Wm2);
    cudaGetSymbolAddress((void**)&Wb1,    g_Wb1);
    cudaGetSymbolAddress((void**)&Wb2,    g_Wb2);

    cudaFuncSetAttribute(attn_kernel, cudaFuncAttributeMaxDynamicSharedMemorySize, ATTN_SMEM);

    const int MPAT = Bn * NPAT;
    const dim3 blk(256);
    const dim3 blkLN(192);   // 192 threads x float4 = 768 = E exactly

    // ---- weight conversion (replayed each graph launch; ~100us) ----
    auto cvt = [&](const float* s, __half* d, int n) {
        cvt_kernel<<<(n / 8 + 255) / 256, blk>>>(s, d, n / 8);
    };
    cvt(patch_W, Wpatch, 768 * 768);
    cvt(in_w,    Win,    12 * 2304 * 768);
    cvt(out_w,   Wout,   12 * 768 * 768);
    cvt(mlp_w1,  Wm1,    12 * 3072 * 768);
    cvt(mlp_w2,  Wm2,    12 * 768 * 3072);
    cvt(br_w1,   Wb1,    1536 * 768);
    cvt(br_w2,   Wb2,    2048 * 1536);

    // ---- patch embedding ----
    patchify_kernel<<<(MPAT * E + 255) / 256, blk>>>(pixel, PT);
    gemm_tc<<<pgrid(MPAT, E), blk>>>(PT, Wpatch, patch_b, nullptr, PE, MPAT, E, E, 0, 0);
    assemble_kernel<<<(Nrow * E + 255) / 256, blk>>>(PE, cls, row_emb, col_emb, X);

    for (int l = 0; l < Ll; l++) {
        ln_kernel<<<Nrow, blkLN>>>(X, ln1_g + l * E, ln1_b + l * E, XN, E, 1);
        gemm_tc<<<pgrid(Nrow, E3), blk>>>(XN, Win + (size_t)l * E3 * E, in_b + (size_t)l * E3,
                                          nullptr, QKV, Nrow, E, E3, 0, 0);
        attn_kernel<<<Bn * HEADS, blk, ATTN_SMEM>>>(QKV, O);
        gemm_tc<<<pgrid(Nrow, E), blk>>>(O, Wout + (size_t)l * E * E, out_b + (size_t)l * E,
                                         X, X, Nrow, E, E, 2, 0);
        ln_kernel<<<Nrow, blkLN>>>(X, ln2_g + l * E, ln2_b + l * E, XN, E, 1);
        gemm_tc<<<pgrid(Nrow, MLPD), blk>>>(XN, Wm1 + (size_t)l * MLPD * E, mlp_b1 + (size_t)l * MLPD,
                                            nullptr, H1, Nrow, E, MLPD, 1, 1);
        gemm_tc<<<pgrid(Nrow, E), blk>>>(H1, Wm2 + (size_t)l * E * MLPD, mlp_b2 + (size_t)l * E,
                                         X, X, Nrow, MLPD, E, 2, 0);
    }

    ln_kernel<<<Nrow, blkLN>>>(X, fin_g, fin_b, XN, E, 1);
    gemm_tc<<<pgrid(Nrow, E2), blk>>>(XN, Wb1, br_b1, nullptr, H1, Nrow, E, E2, 1, 1);
    gemm_tc<<<pgrid(Nrow, OUTD), blk>>>(H1, Wb2, br_b2, nullptr, OUTP, Nrow, E2, OUTD, 0, 0);
    ln_kernel<<<Nrow, blk>>>(OUTP, br_g, br_b, (float*)d_out, OUTD, 0);

    long long mainN = (long long)Nrow * OUTD;
    if ((long long)out_size > mainN) {
        int extra = (int)((long long)out_size - mainN);
        fill_ones_kernel<<<(extra + 255) / 256, blk>>>((float*)d_out + mainN, extra);
    }
}